// round 14
// baseline (speedup 1.0000x reference)
#include <cuda_runtime.h>
#include <cuda_fp16.h>
#include <cstdint>

// ElementUpdate: out[n,:] = h_prev[n,:] + W[z[n]] @ m_curr[n,:]
// N=16384, D=128, S=119, z sorted.
// R14: warp-independent streaming. Prologue converts W to fp16 (L2-resident,
// 3.9MB). Main: CTA = 64 rows; warp = 32-row band x 32-col quarter. Each warp
// finds its own species segments via ballot over its 32 sorted z values, then
// streams B fragments straight from L2 (ld.global.nc) into m16n8k16 MMAs.
// No W SMEM tiles, no fill/barrier convoy: one barrier total (A fill).

static constexpr int D = 128;
static constexpr int NSPEC = 119;
static constexpr int TILE_M = 64;
static constexpr int NT = 256;
static constexpr int HPAD = 136;               // half stride, conflict-free
static constexpr int A_BYTES = TILE_M * HPAD * 2;   // 17408
static constexpr int SMEM_BYTES = A_BYTES;

__device__ __half g_wh[NSPEC * D * D];   // fp16 weights (prologue output)

__device__ __forceinline__ uint32_t pack_h2(float lo, float hi) {
    uint32_t r;
    asm("cvt.rn.f16x2.f32 %0, %1, %2;" : "=r"(r) : "f"(hi), "f"(lo));
    return r;
}

__device__ __forceinline__ void mma_f16(float* d, const uint32_t* a,
                                        uint32_t b0, uint32_t b1) {
    asm volatile(
        "mma.sync.aligned.m16n8k16.row.col.f32.f16.f16.f32 "
        "{%0,%1,%2,%3}, {%4,%5,%6,%7}, {%8,%9}, {%0,%1,%2,%3};"
        : "+f"(d[0]), "+f"(d[1]), "+f"(d[2]), "+f"(d[3])
        : "r"(a[0]), "r"(a[1]), "r"(a[2]), "r"(a[3]), "r"(b0), "r"(b1));
}

// ---------------- prologue: weight fp32 -> fp16 ----------------
__global__ void __launch_bounds__(NT, 4) convert_w(const float* __restrict__ w) {
    int i = blockIdx.x * NT + threadIdx.x;            // over float4 chunks
    float4 v = ((const float4*)w)[i];
    uint2 u;
    u.x = pack_h2(v.x, v.y);
    u.y = pack_h2(v.z, v.w);
    ((uint2*)g_wh)[i] = u;
}

// ---------------- main ----------------
__global__ void __launch_bounds__(NT, 2)
element_update_kernel(const float* __restrict__ h_prev,
                      const float* __restrict__ m_curr,
                      const int* __restrict__ atom_types,
                      float* __restrict__ out) {
    extern __shared__ __align__(16) char smem[];
    __half* sA = (__half*)smem;
    const int tid = threadIdx.x;
    const int lane = tid & 31;
    const int wid = tid >> 5;
    const int R0 = blockIdx.x * TILE_M;

    // ---- A fill: m_curr rows [R0,R0+64) -> fp16 SMEM ----
    #pragma unroll
    for (int j = 0; j < 8; j++) {
        int i = tid + j * NT;
        int r = i >> 5, c4 = (i & 31) << 2;
        float4 v = *(const float4*)(m_curr + (size_t)(R0 + r) * D + c4);
        uint2 u;
        u.x = pack_h2(v.x, v.y);
        u.y = pack_h2(v.z, v.w);
        *(uint2*)(sA + r * HPAD + c4) = u;
    }

    // ---- per-warp geometry: band (32 rows) x quarter (32 cols) ----
    const int band = wid >> 2;           // 0..1
    const int q = wid & 3;               // 0..3
    const int row0 = R0 + band * 32;
    const int lr = lane >> 2;            // 0..7
    const int lc = lane & 3;             // 0..3

    // ---- per-warp segment discovery over its 32 sorted z values ----
    const int zr = atom_types[row0 + lane];
    const int zp = __shfl_up_sync(0xffffffffu, zr, 1);
    const bool bdy = (lane == 0) || (zp != zr);
    unsigned segmask = __ballot_sync(0xffffffffu, bdy);

    __syncthreads();    // A tile visible; the ONLY barrier

    float acc[2][4][4];
    #pragma unroll
    for (int mt = 0; mt < 2; mt++)
        #pragma unroll
        for (int nt = 0; nt < 4; nt++)
            #pragma unroll
            for (int j = 0; j < 4; j++) acc[mt][nt][j] = 0.f;

    const __half* pAb = sA + (band * 32 + lr) * HPAD + lc * 2;

    unsigned m = segmask;
    while (m) {
        const int a = __ffs(m) - 1;
        m &= m - 1;
        const int b = m ? (__ffs(m) - 1) : 32;
        const int s = __shfl_sync(0xffffffffu, zr, a);
        const __half* wbase = g_wh + (size_t)s * (D * D) + (size_t)(q * 32) * D;

        uint32_t am[2][2];
        #pragma unroll
        for (int mt = 0; mt < 2; mt++) {
            int r = mt * 16 + lr;
            am[mt][0] = (r >= a && r < b) ? 0xffffffffu : 0u;
            am[mt][1] = (r + 8 >= a && r + 8 < b) ? 0xffffffffu : 0u;
        }

        #pragma unroll
        for (int ks = 0; ks < 8; ks++) {
            const int k0 = ks * 16;
            uint32_t aF[2][4];
            #pragma unroll
            for (int mt = 0; mt < 2; mt++) {
                const __half* pA = pAb + mt * (16 * HPAD) + k0;
                aF[mt][0] = *(const uint32_t*)(pA) & am[mt][0];
                aF[mt][1] = *(const uint32_t*)(pA + 8 * HPAD) & am[mt][1];
                aF[mt][2] = *(const uint32_t*)(pA + 8) & am[mt][0];
                aF[mt][3] = *(const uint32_t*)(pA + 8 * HPAD + 8) & am[mt][1];
            }
            #pragma unroll
            for (int nt = 0; nt < 4; nt++) {
                const __half* pB = wbase + (size_t)(nt * 8 + lr) * D + k0 + lc * 2;
                uint32_t b0 = __ldg((const uint32_t*)pB);
                uint32_t b1 = __ldg((const uint32_t*)(pB + 8));
                mma_f16(acc[0][nt], aF[0], b0, b1);
                mma_f16(acc[1][nt], aF[1], b0, b1);
            }
        }
    }

    // ---- epilogue: acc + h_prev -> out (coalesced float2) ----
    #pragma unroll
    for (int mt = 0; mt < 2; mt++)
        #pragma unroll
        for (int h = 0; h < 2; h++) {
            const int r = row0 + mt * 16 + 8 * h + lr;
            const float* hp = h_prev + (size_t)r * D;
            float* op = out + (size_t)r * D;
            #pragma unroll
            for (int nt = 0; nt < 4; nt++) {
                const int c = q * 32 + nt * 8 + lc * 2;
                float2 hv = *(const float2*)(hp + c);
                float2 o;
                o.x = hv.x + acc[mt][nt][2 * h + 0];
                o.y = hv.y + acc[mt][nt][2 * h + 1];
                *(float2*)(op + c) = o;
            }
        }
}

extern "C" void kernel_launch(void* const* d_in, const int* in_sizes, int n_in,
                              void* d_out, int out_size) {
    const float* h_prev     = (const float*)d_in[0];
    const float* m_curr     = (const float*)d_in[1];
    const int*   atom_types = (const int*)d_in[2];
    const float* weight     = (const float*)d_in[3];
    float* out = (float*)d_out;

    int n_nodes = in_sizes[0] / D;       // 16384
    int grid = n_nodes / TILE_M;         // 256
    int wgrid = (NSPEC * D * D) / 4 / NT;   // 1904 exact

    cudaFuncSetAttribute(element_update_kernel,
                         cudaFuncAttributeMaxDynamicSharedMemorySize, SMEM_BYTES);

    convert_w<<<wgrid, NT>>>(weight);
    element_update_kernel<<<grid, NT, SMEM_BYTES>>>(h_prev, m_curr, atom_types, out);
}

// round 15
// speedup vs baseline: 1.2739x; 1.2739x over previous
#include <cuda_runtime.h>
#include <cuda_fp16.h>
#include <cstdint>

// ElementUpdate: out[n,:] = h_prev[n,:] + W[z[n]] @ m_curr[n,:]
// N=16384, D=128, S=119, z sorted.
// R15: R9 champion loop + cp.async double-buffered pre-converted fp16 W.
// (R13 retried without its register bugs: no A-fragment register array, no
// indexed pointer array.) Prologue converts W to fp16 once (L2-resident).
// W0 prefetch overlaps A-fill+scan; W(seg+1) prefetch overlaps seg's MMA.

static constexpr int D = 128;
static constexpr int NSPEC = 119;
static constexpr int TILE_M = 64;
static constexpr int NT = 256;
static constexpr int HPAD = 136;               // half stride: 272B row, conflict-free
static constexpr int HDR = 1024;
static constexpr int A_BYTES = TILE_M * HPAD * 2;   // 17408
static constexpr int W_BYTES = D * HPAD * 2;        // 34816 per buffer
static constexpr int SMEM_BYTES = HDR + A_BYTES + 2 * W_BYTES;  // 88064 -> 2 CTAs/SM

__device__ __half g_wh[NSPEC * D * D];   // fp16 weights (prologue output)

__device__ __forceinline__ uint32_t pack_h2(float lo, float hi) {
    uint32_t r;
    asm("cvt.rn.f16x2.f32 %0, %1, %2;" : "=r"(r) : "f"(hi), "f"(lo));
    return r;
}

__device__ __forceinline__ uint32_t smem_u32(const void* p) {
    uint32_t a;
    asm("{ .reg .u64 t; cvta.to.shared.u64 t, %1; cvt.u32.u64 %0, t; }" : "=r"(a) : "l"(p));
    return a;
}

__device__ __forceinline__ void cpa16(uint32_t dst, const void* src) {
    asm volatile("cp.async.ca.shared.global [%0], [%1], 16;" :: "r"(dst), "l"(src));
}
#define CP_COMMIT() asm volatile("cp.async.commit_group;" ::: "memory")
#define CP_WAIT(n)  asm volatile("cp.async.wait_group %0;" :: "n"(n) : "memory")

__device__ __forceinline__ void mma_f16(float* d, const uint32_t* a,
                                        uint32_t b0, uint32_t b1) {
    asm volatile(
        "mma.sync.aligned.m16n8k16.row.col.f32.f16.f16.f32 "
        "{%0,%1,%2,%3}, {%4,%5,%6,%7}, {%8,%9}, {%0,%1,%2,%3};"
        : "+f"(d[0]), "+f"(d[1]), "+f"(d[2]), "+f"(d[3])
        : "r"(a[0]), "r"(a[1]), "r"(a[2]), "r"(a[3]), "r"(b0), "r"(b1));
}

// ---------------- prologue: weight fp32 -> fp16 ----------------
__global__ void __launch_bounds__(NT, 4) convert_w(const float* __restrict__ w) {
    int i = blockIdx.x * NT + threadIdx.x;            // over float4 chunks
    float4 v = ((const float4*)w)[i];
    uint2 u;
    u.x = pack_h2(v.x, v.y);
    u.y = pack_h2(v.z, v.w);
    ((uint2*)g_wh)[i] = u;
}

// ---------------- main ----------------
__global__ void __launch_bounds__(NT, 2)
element_update_kernel(const float* __restrict__ h_prev,
                      const float* __restrict__ m_curr,
                      const int* __restrict__ atom_types,
                      float* __restrict__ out) {
    extern __shared__ __align__(16) char smem[];
    const int tid = threadIdx.x;
    const int lane = tid & 31;
    const int wid = tid >> 5;
    const int R0 = blockIdx.x * TILE_M;

    int* sCnt  = (int*)(smem + 0);
    int* sNseg = (int*)(smem + 32);
    int* sRow  = (int*)(smem + 64);     // up to TILE_M+1
    int* sSpec = (int*)(smem + 384);    // up to TILE_M
    __half* sA  = (__half*)(smem + HDR);
    __half* sW0 = (__half*)(smem + HDR + A_BYTES);
    __half* sW1 = (__half*)(smem + HDR + A_BYTES + W_BYTES);

    const uint32_t sbase = smem_u32(smem);
    const uint32_t wU0 = sbase + HDR + A_BYTES;
    const uint32_t wU1 = wU0 + W_BYTES;

    // fp16 W[s] -> buffer (8 x 16B per thread); caller commits.
    auto issue_w = [&](int s, int b) {
        const __half* src = g_wh + (size_t)s * (D * D);
        uint32_t dU = b ? wU1 : wU0;
        #pragma unroll
        for (int j = 0; j < 8; j++) {
            int i = tid + j * NT;
            int r = i >> 4, c8 = (i & 15) << 3;       // 16 x 16B chunks per row
            cpa16(dU + (uint32_t)(r * HPAD + c8) * 2u, src + r * D + c8);
        }
        CP_COMMIT();
    };

    // s0 LDG first (its latency overlaps the A fill below)
    const int s0 = atom_types[R0];

    // ---- A fill: m_curr -> fp16 SMEM (LDG/cvt/STS, batched LDGs) ----
    #pragma unroll
    for (int j = 0; j < 8; j++) {
        int i = tid + j * NT;
        int r = i >> 5, c4 = (i & 31) << 2;
        float4 v = *(const float4*)(m_curr + (size_t)(R0 + r) * D + c4);
        uint2 u;
        u.x = pack_h2(v.x, v.y);
        u.y = pack_h2(v.z, v.w);
        *(uint2*)(sA + r * HPAD + c4) = u;
    }

    // ---- W0 prefetch (s0 ready by now), transfers overlap scan ----
    issue_w(s0, 0);

    // ---- species-segment scan over TILE_M sorted z values (warps 0-1) ----
    bool bd = false; int wpre = 0, zr = 0;
    if (tid < TILE_M) {
        zr = atom_types[R0 + tid];
        int zp = (tid == 0) ? -1 : atom_types[R0 + tid - 1];
        bd = (zp != zr);
        unsigned msk = __ballot_sync(0xffffffffu, bd);
        wpre = __popc(msk & ((1u << lane) - 1u));
        if (lane == 0) sCnt[wid] = __popc(msk);
    }
    __syncthreads();
    if (tid == 0) {
        int c0 = sCnt[0], c1 = sCnt[1];
        sCnt[2] = c0;
        *sNseg = c0 + c1;
        sRow[c0 + c1] = TILE_M;
    }
    __syncthreads();
    if (tid < TILE_M && bd) {
        int i = (wid ? sCnt[2] : 0) + wpre;
        sRow[i] = tid;
        sSpec[i] = zr;
    }
    __syncthreads();
    const int nseg = *sNseg;

    // ---- W1 prefetch (if any), then wait for W0 ----
    if (nseg > 1) { issue_w(sSpec[1], 1); CP_WAIT(1); }
    else          { CP_WAIT(0); }
    __syncthreads();       // A + W0 visible to all

    // ---- warp geometry: rows [16*wr,+16) x cols [64*wc,+64) ----
    const int wr = wid >> 1;     // 0..3
    const int wc = wid & 1;      // 0..1
    const int rlo = wr * 16;
    const int lr = lane >> 2;    // 0..7
    const int lc = lane & 3;     // 0..3

    float acc[8][4];
    #pragma unroll
    for (int nt = 0; nt < 8; nt++)
        #pragma unroll
        for (int j = 0; j < 4; j++) acc[nt][j] = 0.f;

    const __half* pA0 = sA + (rlo + lr) * HPAD + lc * 2;
    const __half* pA1 = pA0 + 8 * HPAD;
    const int bOff = (wc * 64 + lr) * HPAD + lc * 2;

    for (int seg = 0; seg < nseg; seg++) {
        const int a = sRow[seg];
        const int b = sRow[seg + 1];
        const __half* pB0 = ((seg & 1) ? sW1 : sW0) + bOff;

        if (b > rlo && a < rlo + 16) {
            const int r0 = rlo + lr;
            const uint32_t am0 = (r0 >= a && r0 < b) ? 0xffffffffu : 0u;
            const uint32_t am1 = (r0 + 8 >= a && r0 + 8 < b) ? 0xffffffffu : 0u;

            #pragma unroll
            for (int ks = 0; ks < 8; ks++) {
                const int k0 = ks * 16;
                uint32_t aF[4];
                aF[0] = *(const uint32_t*)(pA0 + k0) & am0;
                aF[1] = *(const uint32_t*)(pA1 + k0) & am1;
                aF[2] = *(const uint32_t*)(pA0 + k0 + 8) & am0;
                aF[3] = *(const uint32_t*)(pA1 + k0 + 8) & am1;
                #pragma unroll
                for (int nt = 0; nt < 8; nt++) {
                    const __half* pB = pB0 + nt * (8 * HPAD) + k0;
                    uint32_t b0 = *(const uint32_t*)(pB);
                    uint32_t b1 = *(const uint32_t*)(pB + 8);
                    mma_f16(acc[nt], aF, b0, b1);
                }
            }
        }

        if (seg + 1 < nseg) {
            __syncthreads();                       // readers done with buf (seg&1)
            if (seg + 2 < nseg) { issue_w(sSpec[seg + 2], seg & 1); CP_WAIT(1); }
            else                { CP_WAIT(0); }
            __syncthreads();                       // next buffer visible
        }
    }

    // ---- epilogue: acc + h_prev -> out (coalesced float2, 32B sectors) ----
    #pragma unroll
    for (int h = 0; h < 2; h++) {
        const int r = R0 + rlo + 8 * h + lr;
        const float* hp = h_prev + (size_t)r * D;
        float* op = out + (size_t)r * D;
        #pragma unroll
        for (int nt = 0; nt < 8; nt++) {
            const int c = wc * 64 + 8 * nt + lc * 2;
            float2 hv = *(const float2*)(hp + c);
            float2 o;
            o.x = hv.x + acc[nt][2 * h + 0];
            o.y = hv.y + acc[nt][2 * h + 1];
            *(float2*)(op + c) = o;
        }
    }
}

extern "C" void kernel_launch(void* const* d_in, const int* in_sizes, int n_in,
                              void* d_out, int out_size) {
    const float* h_prev     = (const float*)d_in[0];
    const float* m_curr     = (const float*)d_in[1];
    const int*   atom_types = (const int*)d_in[2];
    const float* weight     = (const float*)d_in[3];
    float* out = (float*)d_out;

    int n_nodes = in_sizes[0] / D;          // 16384
    int grid = n_nodes / TILE_M;            // 256
    int wgrid = (NSPEC * D * D) / 4 / NT;   // 1904 exact

    cudaFuncSetAttribute(element_update_kernel,
                         cudaFuncAttributeMaxDynamicSharedMemorySize, SMEM_BYTES);

    convert_w<<<wgrid, NT>>>(weight);
    element_update_kernel<<<grid, NT, SMEM_BYTES>>>(h_prev, m_curr, atom_types, out);
}